// round 15
// baseline (speedup 1.0000x reference)
#include <cuda_runtime.h>
#include <cuda_bf16.h>
#include <cstdint>

#define BB 16
#define NN 10000
#define HH 128
#define EE 320000
#define MM (BB * NN)   // 160000 rows
#define DPAD 128       // padded max degree (mean 32, 11+ sigma headroom)
#define NCHUNK 5
#define TILES (MM / 128)                        // 1250
#define TILES_PER_CHUNK (TILES / NCHUNK)        // 250
#define ROWS_PER_CHUNK (TILES_PER_CHUNK * 128)  // 32000

// Scratch (static device allocations are the sanctioned workaround)
__device__ float          g_neighbor[(size_t)MM * HH];  // 82 MB
__device__ __nv_bfloat16  g_embh[(size_t)MM * HH];      // 41 MB bf16 emb copy
__device__ int            g_cur[NN];
__device__ int            g_colbuf[NN * DPAD];          // prescaled (*32) col offsets

// ---------------- helpers ----------------

__device__ __forceinline__ uint32_t f2tf32(float x) {
    uint32_t u;
    asm("cvt.rna.tf32.f32 %0, %1;" : "=r"(u) : "f"(x));
    return u;
}

__device__ __forceinline__ void mma_tf32(float* d, uint32_t a0, uint32_t a1,
                                         uint32_t a2, uint32_t a3,
                                         uint32_t b0, uint32_t b1) {
    asm volatile(
        "mma.sync.aligned.m16n8k8.row.col.f32.tf32.tf32.f32 "
        "{%0,%1,%2,%3}, {%4,%5,%6,%7}, {%8,%9}, {%0,%1,%2,%3};"
        : "+f"(d[0]), "+f"(d[1]), "+f"(d[2]), "+f"(d[3])
        : "r"(a0), "r"(a1), "r"(a2), "r"(a3), "r"(b0), "r"(b1));
}

// ---------------- bucket build ----------------

__global__ void k_zero() {
    int i = blockIdx.x * blockDim.x + threadIdx.x;
    if (i < NN) g_cur[i] = 0;
}

__global__ void k_fill(const int* __restrict__ src, const int* __restrict__ dst) {
    int e = blockIdx.x * blockDim.x + threadIdx.x;
    if (e < EE) {
        int d = dst[e];
        int p = atomicAdd(&g_cur[d], 1);
        if (p < DPAD) g_colbuf[d * DPAD + p] = src[e] * 32;   // prescaled row offset
    }
}

// ---------------- emb -> bf16 copy (one streaming pass) ----------------

__global__ void __launch_bounds__(256) k_conv(const float* __restrict__ emb) {
    size_t i = ((size_t)blockIdx.x * blockDim.x + threadIdx.x) * 4;
    float4 v = *(const float4*)(emb + i);
    __nv_bfloat162 lo = __floats2bfloat162_rn(v.x, v.y);
    __nv_bfloat162 hi = __floats2bfloat162_rn(v.z, v.w);
    uint2 pk;
    pk.x = *reinterpret_cast<uint32_t*>(&lo);
    pk.y = *reinterpret_cast<uint32_t*>(&hi);
    *reinterpret_cast<uint2*>(g_embh + i) = pk;
}

// ---------------- Gather (segment sum), bf16 source: one warp per ROW ------

__global__ void __launch_bounds__(256) k_gather(int row0) {
    int r = row0 + ((blockIdx.x * blockDim.x + threadIdx.x) >> 5);
    int lane = threadIdx.x & 31;
    int b = r / NN, n = r - b * NN;
    int deg = min(g_cur[n], DPAD);
    const int* cols = g_colbuf + n * DPAD;
    const uint2* eb = (const uint2*)(g_embh + (size_t)b * NN * HH) + lane;
    float4 acc = make_float4(0.f, 0.f, 0.f, 0.f);
    int i = 0;
    for (; i + 8 <= deg; i += 8) {
        int c[8];
        #pragma unroll
        for (int j = 0; j < 8; j++) c[j] = cols[i + j];
        uint2 u[8];
        #pragma unroll
        for (int j = 0; j < 8; j++) u[j] = eb[c[j]];
        #pragma unroll
        for (int j = 0; j < 8; j++) {
            float2 f0 = __bfloat1622float2(*reinterpret_cast<__nv_bfloat162*>(&u[j].x));
            float2 f1 = __bfloat1622float2(*reinterpret_cast<__nv_bfloat162*>(&u[j].y));
            acc.x += f0.x; acc.y += f0.y; acc.z += f1.x; acc.w += f1.y;
        }
    }
    for (; i < deg; i++) {
        uint2 u = eb[cols[i]];
        float2 f0 = __bfloat1622float2(*reinterpret_cast<__nv_bfloat162*>(&u.x));
        float2 f1 = __bfloat1622float2(*reinterpret_cast<__nv_bfloat162*>(&u.y));
        acc.x += f0.x; acc.y += f0.y; acc.z += f1.x; acc.w += f1.y;
    }
    float4* op = (float4*)g_neighbor + (size_t)r * 32 + lane;
    *op = acc;
}

// ---------------- Fused MLP (R13 config): 512 thr, 2 CTAs/SM ----------------
// Block: 128x128 tile, 512 threads = 16 warps (4m x 4n), warp tile 32x32.

#define WS_S 136
#define AS_S 36
#define HS_S 132
#define SMEM_FLOATS (4352 + 16896)   // 84992 B -> 2 CTAs/SM

__global__ void __launch_bounds__(512, 2) k_fused(
    const float* __restrict__ emb,
    const int*   __restrict__ mask,
    const float* __restrict__ W1,   // [256,128]
    const float* __restrict__ b1,
    const float* __restrict__ W2,   // [128,128]
    const float* __restrict__ b2,
    float* __restrict__ out,
    int tile0)
{
    extern __shared__ float sm[];
    float* Ws = sm;           // [32][WS_S]
    float* As = sm + 4352;    // [128][AS_S]
    float* Hs = sm + 4352;    // [128][HS_S] (aliases As)

    int t = threadIdx.x;
    int lane = t & 31, wid = t >> 5;
    int gid = lane >> 2, tig = lane & 3;
    int warp_m = wid & 3, warp_n = wid >> 2;   // 4 x 4
    size_t rowbase = (size_t)(tile0 + blockIdx.x) * 128;

    float acc[2][4][4];
    #pragma unroll
    for (int mt = 0; mt < 2; mt++)
        #pragma unroll
        for (int nt = 0; nt < 4; nt++)
            #pragma unroll
            for (int i = 0; i < 4; i++) acc[mt][nt][i] = 0.f;

    #define MMA_CHUNK(Ap, Astride, KOFF) do {                                    \
        _Pragma("unroll")                                                        \
        for (int ks = 0; ks < 4; ks++) {                                         \
            int k0 = ks * 8;                                                     \
            uint32_t bfr[4][2];                                                  \
            _Pragma("unroll")                                                    \
            for (int nt = 0; nt < 4; nt++) {                                     \
                int cb = warp_n * 32 + nt * 8 + gid;                             \
                bfr[nt][0] = __float_as_uint(Ws[(k0 + tig) * WS_S + cb]);        \
                bfr[nt][1] = __float_as_uint(Ws[(k0 + tig + 4) * WS_S + cb]);    \
            }                                                                    \
            _Pragma("unroll")                                                    \
            for (int mt = 0; mt < 2; mt++) {                                     \
                int rb = warp_m * 32 + mt * 16;                                  \
                uint32_t a0 = __float_as_uint((Ap)[(rb + gid) * (Astride) + (KOFF) + k0 + tig]);      \
                uint32_t a1 = __float_as_uint((Ap)[(rb + gid + 8) * (Astride) + (KOFF) + k0 + tig]);  \
                uint32_t a2 = __float_as_uint((Ap)[(rb + gid) * (Astride) + (KOFF) + k0 + tig + 4]);  \
                uint32_t a3 = __float_as_uint((Ap)[(rb + gid + 8) * (Astride) + (KOFF) + k0 + tig + 4]);\
                _Pragma("unroll")                                                \
                for (int nt = 0; nt < 4; nt++)                                   \
                    mma_tf32(acc[mt][nt], a0, a1, a2, a3, bfr[nt][0], bfr[nt][1]);\
            }                                                                    \
        }                                                                        \
    } while (0)

    // ---- phase 1: [neighbor | emb] @ W1, K = 256 ----
    for (int kc = 0; kc < 8; ++kc) {
        const float* A = (kc < 4) ? (const float*)g_neighbor : emb;
        int kof = (kc & 3) * 32;
        #pragma unroll
        for (int j = 0; j < 2; j++) {
            int idx = t + 512 * j;
            int row = idx >> 3, kq = idx & 7;
            float4 v = *(const float4*)(A + (rowbase + row) * 128 + kof + kq * 4);
            float* p = &As[row * AS_S + kq * 4];
            p[0] = __uint_as_float(f2tf32(v.x));
            p[1] = __uint_as_float(f2tf32(v.y));
            p[2] = __uint_as_float(f2tf32(v.z));
            p[3] = __uint_as_float(f2tf32(v.w));
        }
        #pragma unroll
        for (int j = 0; j < 2; j++) {
            int idx = t + 512 * j;
            int kk = idx >> 5, cq = idx & 31;
            float4 v = *(const float4*)(W1 + (size_t)(kc * 32 + kk) * 128 + cq * 4);
            float* p = &Ws[kk * WS_S + cq * 4];
            p[0] = __uint_as_float(f2tf32(v.x));
            p[1] = __uint_as_float(f2tf32(v.y));
            p[2] = __uint_as_float(f2tf32(v.z));
            p[3] = __uint_as_float(f2tf32(v.w));
        }
        __syncthreads();
        MMA_CHUNK(As, AS_S, 0);
        __syncthreads();
    }

    // ---- epilogue 1: h = relu(acc + b1) -> Hs (tf32); reset acc ----
    #pragma unroll
    for (int mt = 0; mt < 2; mt++) {
        #pragma unroll
        for (int half = 0; half < 2; half++) {
            int r = warp_m * 32 + mt * 16 + gid + half * 8;
            #pragma unroll
            for (int nt = 0; nt < 4; nt++) {
                int c = warp_n * 32 + nt * 8 + tig * 2;
                float2 bv = *(const float2*)(b1 + c);
                float hx = fmaxf(acc[mt][nt][half * 2 + 0] + bv.x, 0.f);
                float hy = fmaxf(acc[mt][nt][half * 2 + 1] + bv.y, 0.f);
                Hs[r * HS_S + c]     = __uint_as_float(f2tf32(hx));
                Hs[r * HS_S + c + 1] = __uint_as_float(f2tf32(hy));
            }
        }
    }
    #pragma unroll
    for (int mt = 0; mt < 2; mt++)
        #pragma unroll
        for (int nt = 0; nt < 4; nt++)
            #pragma unroll
            for (int i = 0; i < 4; i++) acc[mt][nt][i] = 0.f;

    // ---- phase 2: h @ W2, K = 128, A from Hs ----
    for (int kc = 0; kc < 4; ++kc) {
        __syncthreads();   // Hs fully written (kc=0) / Ws free (kc>0)
        #pragma unroll
        for (int j = 0; j < 2; j++) {
            int idx = t + 512 * j;
            int kk = idx >> 5, cq = idx & 31;
            float4 v = *(const float4*)(W2 + (size_t)(kc * 32 + kk) * 128 + cq * 4);
            float* p = &Ws[kk * WS_S + cq * 4];
            p[0] = __uint_as_float(f2tf32(v.x));
            p[1] = __uint_as_float(f2tf32(v.y));
            p[2] = __uint_as_float(f2tf32(v.z));
            p[3] = __uint_as_float(f2tf32(v.w));
        }
        __syncthreads();
        MMA_CHUNK(Hs, HS_S, kc * 32);
    }

    // ---- epilogue 2: bias + mask select ----
    #pragma unroll
    for (int mt = 0; mt < 2; mt++) {
        #pragma unroll
        for (int half = 0; half < 2; half++) {
            size_t r = rowbase + warp_m * 32 + mt * 16 + gid + half * 8;
            int m = mask[r];
            #pragma unroll
            for (int nt = 0; nt < 4; nt++) {
                int c = warp_n * 32 + nt * 8 + tig * 2;
                float2 o;
                if (m) {
                    float2 bv = *(const float2*)(b2 + c);
                    o.x = acc[mt][nt][half * 2 + 0] + bv.x;
                    o.y = acc[mt][nt][half * 2 + 1] + bv.y;
                } else {
                    o = *(const float2*)(emb + r * 128 + c);
                }
                *(float2*)(out + r * 128 + c) = o;
            }
        }
    }
}

// ---------------- launch: priority fork-join pipeline ----------------

static cudaStream_t s_g = nullptr, s_m = nullptr;
static cudaEvent_t  s_evFork = nullptr, s_evJoin = nullptr;
static cudaEvent_t  s_ev[NCHUNK];

extern "C" void kernel_launch(void* const* d_in, const int* in_sizes, int n_in,
                              void* d_out, int out_size) {
    const float* emb  = (const float*)d_in[0];
    const int*   mask = (const int*)d_in[1];
    const int*   eidx = (const int*)d_in[2];
    const float* W1   = (const float*)d_in[3];
    const float* b1   = (const float*)d_in[4];
    const float* W2   = (const float*)d_in[5];
    const float* b2   = (const float*)d_in[6];
    const int* src = eidx;
    const int* dst = eidx + EE;
    float* out = (float*)d_out;

    if (s_g == nullptr) {   // first (correctness, uncaptured) call only
        int prLo, prHi;
        cudaDeviceGetStreamPriorityRange(&prLo, &prHi);
        cudaStreamCreateWithPriority(&s_g, cudaStreamNonBlocking, prLo);
        cudaStreamCreateWithPriority(&s_m, cudaStreamNonBlocking, prHi);
        cudaEventCreateWithFlags(&s_evFork, cudaEventDisableTiming);
        cudaEventCreateWithFlags(&s_evJoin, cudaEventDisableTiming);
        for (int c = 0; c < NCHUNK; c++)
            cudaEventCreateWithFlags(&s_ev[c], cudaEventDisableTiming);
        cudaFuncSetAttribute(k_fused, cudaFuncAttributeMaxDynamicSharedMemorySize,
                             SMEM_FLOATS * 4);
    }

    // bucket build + bf16 conversion on origin stream, then fork
    k_zero<<<(NN + 255) / 256, 256>>>();
    k_fill<<<(EE + 255) / 256, 256>>>(src, dst);
    k_conv<<<(MM * HH) / (256 * 4), 256>>>(emb);
    cudaEventRecord(s_evFork, 0);
    cudaStreamWaitEvent(s_g, s_evFork, 0);
    cudaStreamWaitEvent(s_m, s_evFork, 0);

    // eager gathers on low-priority stream
    for (int c = 0; c < NCHUNK; c++) {
        k_gather<<<ROWS_PER_CHUNK / 8, 256, 0, s_g>>>(c * ROWS_PER_CHUNK);
        cudaEventRecord(s_ev[c], s_g);
    }
    // fused chain on greatest-priority stream, gated per chunk
    for (int c = 0; c < NCHUNK; c++) {
        cudaStreamWaitEvent(s_m, s_ev[c], 0);
        k_fused<<<TILES_PER_CHUNK, 512, SMEM_FLOATS * 4, s_m>>>(
            emb, mask, W1, b1, W2, b2, out, c * TILES_PER_CHUNK);
    }

    // join back to origin stream
    cudaEventRecord(s_evJoin, s_m);
    cudaStreamWaitEvent(0, s_evJoin, 0);
}

// round 16
// speedup vs baseline: 1.4901x; 1.4901x over previous
#include <cuda_runtime.h>
#include <cuda_bf16.h>
#include <cstdint>

#define BB 16
#define NN 10000
#define HH 128
#define EE 320000
#define MM (BB * NN)   // 160000 rows
#define DPAD 128       // padded max degree (mean 32, 11+ sigma headroom)
#define NCHUNK 5
#define TILES (MM / 128)                        // 1250
#define TILES_PER_CHUNK (TILES / NCHUNK)        // 250
#define ROWS_PER_CHUNK (TILES_PER_CHUNK * 128)  // 32000

// Scratch (static device allocations are the sanctioned workaround)
__device__ float          g_neighbor[(size_t)MM * HH];  // 82 MB
__device__ __nv_bfloat16  g_embh[(size_t)MM * HH];      // 41 MB bf16 emb copy
__device__ int            g_cur[NN];
__device__ int            g_colbuf[NN * DPAD];          // prescaled (*32) col offsets

// ---------------- helpers ----------------

__device__ __forceinline__ uint32_t f2tf32(float x) {
    uint32_t u;
    asm("cvt.rna.tf32.f32 %0, %1;" : "=r"(u) : "f"(x));
    return u;
}

__device__ __forceinline__ void mma_tf32(float* d, uint32_t a0, uint32_t a1,
                                         uint32_t a2, uint32_t a3,
                                         uint32_t b0, uint32_t b1) {
    asm volatile(
        "mma.sync.aligned.m16n8k8.row.col.f32.tf32.tf32.f32 "
        "{%0,%1,%2,%3}, {%4,%5,%6,%7}, {%8,%9}, {%0,%1,%2,%3};"
        : "+f"(d[0]), "+f"(d[1]), "+f"(d[2]), "+f"(d[3])
        : "r"(a0), "r"(a1), "r"(a2), "r"(a3), "r"(b0), "r"(b1));
}

// ---------------- bucket build ----------------

__global__ void k_zero() {
    int i = blockIdx.x * blockDim.x + threadIdx.x;
    if (i < NN) g_cur[i] = 0;
}

__global__ void k_fill(const int* __restrict__ src, const int* __restrict__ dst) {
    int e = blockIdx.x * blockDim.x + threadIdx.x;
    if (e < EE) {
        int d = dst[e];
        int p = atomicAdd(&g_cur[d], 1);
        if (p < DPAD) g_colbuf[d * DPAD + p] = src[e] * 32;   // prescaled row offset
    }
}

// ---------------- emb -> bf16 copy (one streaming pass) ----------------

__global__ void __launch_bounds__(256) k_conv(const float* __restrict__ emb) {
    size_t i = ((size_t)blockIdx.x * blockDim.x + threadIdx.x) * 4;
    float4 v = *(const float4*)(emb + i);
    __nv_bfloat162 lo = __floats2bfloat162_rn(v.x, v.y);
    __nv_bfloat162 hi = __floats2bfloat162_rn(v.z, v.w);
    uint2 pk;
    pk.x = *reinterpret_cast<uint32_t*>(&lo);
    pk.y = *reinterpret_cast<uint32_t*>(&hi);
    *reinterpret_cast<uint2*>(g_embh + i) = pk;
}

// ---------------- Gather (segment sum), bf16 source: one warp per ROW ------

__global__ void __launch_bounds__(256) k_gather(int row0) {
    int r = row0 + ((blockIdx.x * blockDim.x + threadIdx.x) >> 5);
    int lane = threadIdx.x & 31;
    int b = r / NN, n = r - b * NN;
    int deg = min(g_cur[n], DPAD);
    const int* cols = g_colbuf + n * DPAD;
    const uint2* eb = (const uint2*)(g_embh + (size_t)b * NN * HH) + lane;
    float4 acc = make_float4(0.f, 0.f, 0.f, 0.f);
    int i = 0;
    for (; i + 8 <= deg; i += 8) {
        int c[8];
        #pragma unroll
        for (int j = 0; j < 8; j++) c[j] = cols[i + j];
        uint2 u[8];
        #pragma unroll
        for (int j = 0; j < 8; j++) u[j] = eb[c[j]];
        #pragma unroll
        for (int j = 0; j < 8; j++) {
            float2 f0 = __bfloat1622float2(*reinterpret_cast<__nv_bfloat162*>(&u[j].x));
            float2 f1 = __bfloat1622float2(*reinterpret_cast<__nv_bfloat162*>(&u[j].y));
            acc.x += f0.x; acc.y += f0.y; acc.z += f1.x; acc.w += f1.y;
        }
    }
    for (; i < deg; i++) {
        uint2 u = eb[cols[i]];
        float2 f0 = __bfloat1622float2(*reinterpret_cast<__nv_bfloat162*>(&u.x));
        float2 f1 = __bfloat1622float2(*reinterpret_cast<__nv_bfloat162*>(&u.y));
        acc.x += f0.x; acc.y += f0.y; acc.z += f1.x; acc.w += f1.y;
    }
    float4* op = (float4*)g_neighbor + (size_t)r * 32 + lane;
    *op = acc;
}

// ---------------- Fused MLP (R13 config): 512 thr, 2 CTAs/SM ----------------
// Block: 128x128 tile, 512 threads = 16 warps (4m x 4n), warp tile 32x32.

#define WS_S 136
#define AS_S 36
#define HS_S 132
#define SMEM_FLOATS (4352 + 16896)   // 84992 B -> 2 CTAs/SM

__global__ void __launch_bounds__(512, 2) k_fused(
    const float* __restrict__ emb,
    const int*   __restrict__ mask,
    const float* __restrict__ W1,   // [256,128]
    const float* __restrict__ b1,
    const float* __restrict__ W2,   // [128,128]
    const float* __restrict__ b2,
    float* __restrict__ out,
    int tile0)
{
    extern __shared__ float sm[];
    float* Ws = sm;           // [32][WS_S]
    float* As = sm + 4352;    // [128][AS_S]
    float* Hs = sm + 4352;    // [128][HS_S] (aliases As)

    int t = threadIdx.x;
    int lane = t & 31, wid = t >> 5;
    int gid = lane >> 2, tig = lane & 3;
    int warp_m = wid & 3, warp_n = wid >> 2;   // 4 x 4
    size_t rowbase = (size_t)(tile0 + blockIdx.x) * 128;

    float acc[2][4][4];
    #pragma unroll
    for (int mt = 0; mt < 2; mt++)
        #pragma unroll
        for (int nt = 0; nt < 4; nt++)
            #pragma unroll
            for (int i = 0; i < 4; i++) acc[mt][nt][i] = 0.f;

    #define MMA_CHUNK(Ap, Astride, KOFF) do {                                    \
        _Pragma("unroll")                                                        \
        for (int ks = 0; ks < 4; ks++) {                                         \
            int k0 = ks * 8;                                                     \
            uint32_t bfr[4][2];                                                  \
            _Pragma("unroll")                                                    \
            for (int nt = 0; nt < 4; nt++) {                                     \
                int cb = warp_n * 32 + nt * 8 + gid;                             \
                bfr[nt][0] = __float_as_uint(Ws[(k0 + tig) * WS_S + cb]);        \
                bfr[nt][1] = __float_as_uint(Ws[(k0 + tig + 4) * WS_S + cb]);    \
            }                                                                    \
            _Pragma("unroll")                                                    \
            for (int mt = 0; mt < 2; mt++) {                                     \
                int rb = warp_m * 32 + mt * 16;                                  \
                uint32_t a0 = __float_as_uint((Ap)[(rb + gid) * (Astride) + (KOFF) + k0 + tig]);      \
                uint32_t a1 = __float_as_uint((Ap)[(rb + gid + 8) * (Astride) + (KOFF) + k0 + tig]);  \
                uint32_t a2 = __float_as_uint((Ap)[(rb + gid) * (Astride) + (KOFF) + k0 + tig + 4]);  \
                uint32_t a3 = __float_as_uint((Ap)[(rb + gid + 8) * (Astride) + (KOFF) + k0 + tig + 4]);\
                _Pragma("unroll")                                                \
                for (int nt = 0; nt < 4; nt++)                                   \
                    mma_tf32(acc[mt][nt], a0, a1, a2, a3, bfr[nt][0], bfr[nt][1]);\
            }                                                                    \
        }                                                                        \
    } while (0)

    // ---- phase 1: [neighbor | emb] @ W1, K = 256 ----
    for (int kc = 0; kc < 8; ++kc) {
        const float* A = (kc < 4) ? (const float*)g_neighbor : emb;
        int kof = (kc & 3) * 32;
        #pragma unroll
        for (int j = 0; j < 2; j++) {
            int idx = t + 512 * j;
            int row = idx >> 3, kq = idx & 7;
            float4 v = *(const float4*)(A + (rowbase + row) * 128 + kof + kq * 4);
            float* p = &As[row * AS_S + kq * 4];
            p[0] = __uint_as_float(f2tf32(v.x));
            p[1] = __uint_as_float(f2tf32(v.y));
            p[2] = __uint_as_float(f2tf32(v.z));
            p[3] = __uint_as_float(f2tf32(v.w));
        }
        #pragma unroll
        for (int j = 0; j < 2; j++) {
            int idx = t + 512 * j;
            int kk = idx >> 5, cq = idx & 31;
            float4 v = *(const float4*)(W1 + (size_t)(kc * 32 + kk) * 128 + cq * 4);
            float* p = &Ws[kk * WS_S + cq * 4];
            p[0] = __uint_as_float(f2tf32(v.x));
            p[1] = __uint_as_float(f2tf32(v.y));
            p[2] = __uint_as_float(f2tf32(v.z));
            p[3] = __uint_as_float(f2tf32(v.w));
        }
        __syncthreads();
        MMA_CHUNK(As, AS_S, 0);
        __syncthreads();
    }

    // ---- epilogue 1: h = relu(acc + b1) -> Hs (tf32); reset acc ----
    #pragma unroll
    for (int mt = 0; mt < 2; mt++) {
        #pragma unroll
        for (int half = 0; half < 2; half++) {
            int r = warp_m * 32 + mt * 16 + gid + half * 8;
            #pragma unroll
            for (int nt = 0; nt < 4; nt++) {
                int c = warp_n * 32 + nt * 8 + tig * 2;
                float2 bv = *(const float2*)(b1 + c);
                float hx = fmaxf(acc[mt][nt][half * 2 + 0] + bv.x, 0.f);
                float hy = fmaxf(acc[mt][nt][half * 2 + 1] + bv.y, 0.f);
                Hs[r * HS_S + c]     = __uint_as_float(f2tf32(hx));
                Hs[r * HS_S + c + 1] = __uint_as_float(f2tf32(hy));
            }
        }
    }
    #pragma unroll
    for (int mt = 0; mt < 2; mt++)
        #pragma unroll
        for (int nt = 0; nt < 4; nt++)
            #pragma unroll
            for (int i = 0; i < 4; i++) acc[mt][nt][i] = 0.f;

    // ---- phase 2: h @ W2, K = 128, A from Hs ----
    for (int kc = 0; kc < 4; ++kc) {
        __syncthreads();   // Hs fully written (kc=0) / Ws free (kc>0)
        #pragma unroll
        for (int j = 0; j < 2; j++) {
            int idx = t + 512 * j;
            int kk = idx >> 5, cq = idx & 31;
            float4 v = *(const float4*)(W2 + (size_t)(kc * 32 + kk) * 128 + cq * 4);
            float* p = &Ws[kk * WS_S + cq * 4];
            p[0] = __uint_as_float(f2tf32(v.x));
            p[1] = __uint_as_float(f2tf32(v.y));
            p[2] = __uint_as_float(f2tf32(v.z));
            p[3] = __uint_as_float(f2tf32(v.w));
        }
        __syncthreads();
        MMA_CHUNK(Hs, HS_S, kc * 32);
    }

    // ---- epilogue 2: bias + mask select ----
    #pragma unroll
    for (int mt = 0; mt < 2; mt++) {
        #pragma unroll
        for (int half = 0; half < 2; half++) {
            size_t r = rowbase + warp_m * 32 + mt * 16 + gid + half * 8;
            int m = mask[r];
            #pragma unroll
            for (int nt = 0; nt < 4; nt++) {
                int c = warp_n * 32 + nt * 8 + tig * 2;
                float2 o;
                if (m) {
                    float2 bv = *(const float2*)(b2 + c);
                    o.x = acc[mt][nt][half * 2 + 0] + bv.x;
                    o.y = acc[mt][nt][half * 2 + 1] + bv.y;
                } else {
                    o = *(const float2*)(emb + r * 128 + c);
                }
                *(float2*)(out + r * 128 + c) = o;
            }
        }
    }
}

// ---------------- launch: priority fork-join pipeline ----------------

static cudaStream_t s_g = nullptr, s_m = nullptr;
static cudaEvent_t  s_evFork = nullptr, s_evJoin = nullptr;
static cudaEvent_t  s_ev[NCHUNK];

extern "C" void kernel_launch(void* const* d_in, const int* in_sizes, int n_in,
                              void* d_out, int out_size) {
    const float* emb  = (const float*)d_in[0];
    const int*   mask = (const int*)d_in[1];
    const int*   eidx = (const int*)d_in[2];
    const float* W1   = (const float*)d_in[3];
    const float* b1   = (const float*)d_in[4];
    const float* W2   = (const float*)d_in[5];
    const float* b2   = (const float*)d_in[6];
    const int* src = eidx;
    const int* dst = eidx + EE;
    float* out = (float*)d_out;

    if (s_g == nullptr) {   // first (correctness, uncaptured) call only
        int prLo, prHi;
        cudaDeviceGetStreamPriorityRange(&prLo, &prHi);
        cudaStreamCreateWithPriority(&s_g, cudaStreamNonBlocking, prLo);
        cudaStreamCreateWithPriority(&s_m, cudaStreamNonBlocking, prHi);
        cudaEventCreateWithFlags(&s_evFork, cudaEventDisableTiming);
        cudaEventCreateWithFlags(&s_evJoin, cudaEventDisableTiming);
        for (int c = 0; c < NCHUNK; c++)
            cudaEventCreateWithFlags(&s_ev[c], cudaEventDisableTiming);
        cudaFuncSetAttribute(k_fused, cudaFuncAttributeMaxDynamicSharedMemorySize,
                             SMEM_FLOATS * 4);
    }

    // bucket build + bf16 conversion on origin stream, then fork
    k_zero<<<(NN + 255) / 256, 256>>>();
    k_fill<<<(EE + 255) / 256, 256>>>(src, dst);
    k_conv<<<(MM * HH) / (256 * 4), 256>>>(emb);
    cudaEventRecord(s_evFork, 0);
    cudaStreamWaitEvent(s_g, s_evFork, 0);
    cudaStreamWaitEvent(s_m, s_evFork, 0);

    // eager gathers on low-priority stream
    for (int c = 0; c < NCHUNK; c++) {
        k_gather<<<ROWS_PER_CHUNK / 8, 256, 0, s_g>>>(c * ROWS_PER_CHUNK);
        cudaEventRecord(s_ev[c], s_g);
    }
    // fused chain on greatest-priority stream, gated per chunk
    for (int c = 0; c < NCHUNK; c++) {
        cudaStreamWaitEvent(s_m, s_ev[c], 0);
        k_fused<<<TILES_PER_CHUNK, 512, SMEM_FLOATS * 4, s_m>>>(
            emb, mask, W1, b1, W2, b2, out, c * TILES_PER_CHUNK);
    }

    // join back to origin stream
    cudaEventRecord(s_evJoin, s_m);
    cudaStreamWaitEvent(0, s_evJoin, 0);
}